// round 4
// baseline (speedup 1.0000x reference)
#include <cuda_runtime.h>
#include <math.h>

#define NN   50000
#define NE   800000
#define NEP  850000          // NE + NN self loops
#define FIN  512
#define H1V  8
#define C1V  32
#define D1V  256             // H1V*C1V
#define D2V  64
#define NEG_SLOPE 0.2f
#define EPS_SM 1e-16f

// ---------------- scratch (device globals; no allocs) ----------------
__device__ int   g_flag;                       // 1 = edge_index is int64
__device__ int   g_src[NE];
__device__ int   g_dst[NE];
__device__ float g_h1[(size_t)NN * D1V];       // x@W1
__device__ float g_agg1[(size_t)NN * D1V];     // layer1 aggregate -> relu'd in place
__device__ float g_h2[(size_t)NN * D2V];       // h1o@W2
__device__ float g_agg2[(size_t)NN * D2V];     // layer2 aggregate
__device__ float g_as1[NN * H1V], g_ad1[NN * H1V], g_m1[NN * H1V], g_s1[NN * H1V];
__device__ float g_as2[NN],       g_ad2[NN],       g_m2[NN],       g_s2[NN];
__device__ float g_ex1[(size_t)NEP * H1V];
__device__ float g_ex2[NEP];

// ---------------- helpers ----------------
__device__ __forceinline__ void atomicMaxFloat(float* addr, float value) {
    if (value >= 0.0f) atomicMax((int*)addr, __float_as_int(value));
    else               atomicMin((unsigned int*)addr, __float_as_uint(value));
}

__device__ __forceinline__ void edge_sd(int e, int& s, int& d) {
    if (e < NE) { s = __ldg(&g_src[e]); d = __ldg(&g_dst[e]); }
    else        { s = d = e - NE; }            // self loop
}

__device__ __forceinline__ float lrelu(float v) {
    return v > 0.f ? v : NEG_SLOPE * v;
}

// ---------------- edge-index width detection & normalization ----------------
__global__ void detect_kernel(const void* ei) {
    const long long* p = (const long long*)ei;
    int ok = 1;
    for (int i = 0; i < 64; i++) {
        long long v = p[i];
        if (v < 0 || v >= NN) { ok = 0; break; }
    }
    g_flag = ok;
}

__global__ void convert_kernel(const void* ei) {
    int i = blockIdx.x * blockDim.x + threadIdx.x;
    if (i >= 2 * NE) return;
    int v = g_flag ? (int)((const long long*)ei)[i] : ((const int*)ei)[i];
    if (i < NE) g_src[i] = v;
    else        g_dst[i - NE] = v;
}

__global__ void init_kernel() {
    int i = blockIdx.x * blockDim.x + threadIdx.x;
    if (i < NN * H1V) { g_m1[i] = -INFINITY; g_s1[i] = 0.0f; }
    if (i < NN)       { g_m2[i] = -INFINITY; g_s2[i] = 0.0f; }
}

// ---------------- register-tiled SGEMM: C[M,Nn] = A[M,K] @ B[K,Nn] ----------------
template<int BM, int BN, int BK, int TM, int TN>
__global__ void __launch_bounds__(256)
sgemm_kernel(const float* __restrict__ A, const float* __restrict__ B,
             float* __restrict__ C, int M, int Nn, int K) {
    constexpr int THREADS = (BM / TM) * (BN / TN);
    __shared__ float As[BK][BM];
    __shared__ float Bs[BK][BN];
    const int tid = threadIdx.y * blockDim.x + threadIdx.x;
    const int m0 = blockIdx.x * BM;
    const int n0 = blockIdx.y * BN;

    float acc[TM][TN];
#pragma unroll
    for (int i = 0; i < TM; i++)
#pragma unroll
        for (int j = 0; j < TN; j++) acc[i][j] = 0.0f;

    for (int k0 = 0; k0 < K; k0 += BK) {
        // A tile: BM x BK (transposed into As), float4 along K
#pragma unroll
        for (int t = tid; t < BM * BK / 4; t += THREADS) {
            int row = t / (BK / 4);
            int q   = t % (BK / 4);
            float4 v = make_float4(0.f, 0.f, 0.f, 0.f);
            if (m0 + row < M)
                v = *reinterpret_cast<const float4*>(&A[(size_t)(m0 + row) * K + k0 + q * 4]);
            As[q * 4 + 0][row] = v.x;
            As[q * 4 + 1][row] = v.y;
            As[q * 4 + 2][row] = v.z;
            As[q * 4 + 3][row] = v.w;
        }
        // B tile: BK x BN (Nn is a multiple of BN, K a multiple of BK: no guards)
#pragma unroll
        for (int t = tid; t < BK * BN / 4; t += THREADS) {
            int row = t / (BN / 4);
            int col = t % (BN / 4);
            float4 v = *reinterpret_cast<const float4*>(&B[(size_t)(k0 + row) * Nn + n0 + col * 4]);
            *reinterpret_cast<float4*>(&Bs[row][col * 4]) = v;
        }
        __syncthreads();

#pragma unroll
        for (int k = 0; k < BK; k++) {
            float ra[TM], rb[TN];
#pragma unroll
            for (int i = 0; i < TM; i++) ra[i] = As[k][threadIdx.y * TM + i];
#pragma unroll
            for (int j = 0; j < TN; j++) rb[j] = Bs[k][threadIdx.x * TN + j];
#pragma unroll
            for (int i = 0; i < TM; i++)
#pragma unroll
                for (int j = 0; j < TN; j++) acc[i][j] += ra[i] * rb[j];
        }
        __syncthreads();
    }

#pragma unroll
    for (int i = 0; i < TM; i++) {
        int r = m0 + threadIdx.y * TM + i;
        if (r < M) {
#pragma unroll
            for (int j = 0; j < TN; j++)
                C[(size_t)r * Nn + n0 + threadIdx.x * TN + j] = acc[i][j];
        }
    }
}

// ---------------- per-node attention dot products ----------------
__global__ void dots_kernel(const float* __restrict__ h, const float* __restrict__ av_s,
                            const float* __restrict__ av_d, float* __restrict__ oas,
                            float* __restrict__ oad, int heads, int c) {
    int i = blockIdx.x * blockDim.x + threadIdx.x;   // i = node*heads + head
    if (i >= NN * heads) return;
    int hd = i % heads;
    const float* row = h + (size_t)i * c;
    float x1 = 0.f, x2 = 0.f;
    for (int j = 0; j < c; j++) {
        float v = row[j];
        x1 += v * __ldg(&av_s[hd * c + j]);
        x2 += v * __ldg(&av_d[hd * c + j]);
    }
    oas[i] = x1;
    oad[i] = x2;
}

// ---------------- vectorized group loads (HEADS floats per node) ----------------
template<int HEADS>
__device__ __forceinline__ void load_group(const float* __restrict__ p, int node, float* out) {
    if (HEADS == 8) {
        float4 a = __ldg((const float4*)(p + node * 8));
        float4 b = __ldg((const float4*)(p + node * 8 + 4));
        out[0]=a.x; out[1]=a.y; out[2]=a.z; out[3]=a.w;
        out[4]=b.x; out[5]=b.y; out[6]=b.z; out[7]=b.w;
    } else {
        out[0] = __ldg(p + node);
    }
}

// ---------------- edge pass A: segment max ----------------
template<int HEADS>
__global__ void edge_max_kernel(const float* __restrict__ oas, const float* __restrict__ oad,
                                float* m) {
    int e = blockIdx.x * blockDim.x + threadIdx.x;
    if (e >= NEP) return;
    int s, d; edge_sd(e, s, d);
    float vs[HEADS], vd[HEADS];
    load_group<HEADS>(oas, s, vs);
    load_group<HEADS>(oad, d, vd);
#pragma unroll
    for (int h = 0; h < HEADS; h++)
        atomicMaxFloat(&m[d * HEADS + h], lrelu(vs[h] + vd[h]));
}

// ---------------- edge pass B: exp + segment sum ----------------
template<int HEADS>
__global__ void edge_exp_kernel(const float* __restrict__ oas, const float* __restrict__ oad,
                                const float* __restrict__ m, float* __restrict__ exbuf,
                                float* ssum) {
    int e = blockIdx.x * blockDim.x + threadIdx.x;
    if (e >= NEP) return;
    int s, d; edge_sd(e, s, d);
    float vs[HEADS], vd[HEADS], vm[HEADS], ex[HEADS];
    load_group<HEADS>(oas, s, vs);
    load_group<HEADS>(oad, d, vd);
    load_group<HEADS>(m,   d, vm);
#pragma unroll
    for (int h = 0; h < HEADS; h++) {
        ex[h] = __expf(lrelu(vs[h] + vd[h]) - vm[h]);
        atomicAdd(&ssum[d * HEADS + h], ex[h]);
    }
    if (HEADS == 8) {
        float4* o = (float4*)(exbuf + (size_t)e * 8);
        o[0] = make_float4(ex[0], ex[1], ex[2], ex[3]);
        o[1] = make_float4(ex[4], ex[5], ex[6], ex[7]);
    } else {
        exbuf[e] = ex[0];
    }
}

// ---------------- edge pass C: weighted message aggregation (warp per edge) ----------------
// Each lane owns PER = HEADS*C/32 contiguous channels; for layer 1 (C=32, PER=8) and
// layer 2 (HEADS=1, C=64, PER=2) a lane's chunk lies inside ONE head -> one alpha per lane.
template<int HEADS, int C>
__global__ void edge_agg_kernel(const float* __restrict__ hsrc, const float* __restrict__ exbuf,
                                const float* __restrict__ ssum, float* __restrict__ agg) {
    constexpr int D   = HEADS * C;
    constexpr int PER = D / 32;
    int w = (blockIdx.x * blockDim.x + threadIdx.x) >> 5;
    int lane = threadIdx.x & 31;
    if (w >= NEP) return;
    int s, d; edge_sd(w, s, d);
    const int base = lane * PER;
    const int h    = base / C;   // constant across the lane's PER channels
    float alpha = __ldg(&exbuf[(size_t)w * HEADS + h]) /
                  (__ldg(&ssum[d * HEADS + h]) + EPS_SM);
    const float* sp = hsrc + (size_t)s * D + base;
    float*       ap = agg  + (size_t)d * D + base;
    if (PER >= 4) {
#pragma unroll
        for (int j = 0; j < PER; j += 4) {
            float4 v = __ldg((const float4*)(sp + j));
            atomicAdd(ap + j + 0, v.x * alpha);
            atomicAdd(ap + j + 1, v.y * alpha);
            atomicAdd(ap + j + 2, v.z * alpha);
            atomicAdd(ap + j + 3, v.w * alpha);
        }
    } else {
#pragma unroll
        for (int q = 0; q < PER; q++)
            atomicAdd(ap + q, __ldg(sp + q) * alpha);
    }
}

// ---------------- bias + relu (in place on g_agg1) ----------------
__global__ void relu_bias_kernel(const float* __restrict__ b) {
    size_t i = (size_t)blockIdx.x * blockDim.x + threadIdx.x;
    if (i >= (size_t)NN * D1V) return;
    float v = g_agg1[i] + __ldg(&b[i % D1V]);
    g_agg1[i] = v > 0.f ? v : 0.f;
}

// ---------------- bias + log_softmax over 64 classes (warp per node) ----------------
__global__ void logsoftmax_kernel(const float* __restrict__ b, float* __restrict__ out) {
    int node = blockIdx.x * (blockDim.x >> 5) + (threadIdx.x >> 5);
    int lane = threadIdx.x & 31;
    if (node >= NN) return;
    float v0 = g_agg2[(size_t)node * D2V + lane]      + __ldg(&b[lane]);
    float v1 = g_agg2[(size_t)node * D2V + 32 + lane] + __ldg(&b[32 + lane]);
    float mx = fmaxf(v0, v1);
#pragma unroll
    for (int o = 16; o; o >>= 1) mx = fmaxf(mx, __shfl_xor_sync(0xFFFFFFFFu, mx, o));
    float se = __expf(v0 - mx) + __expf(v1 - mx);
#pragma unroll
    for (int o = 16; o; o >>= 1) se += __shfl_xor_sync(0xFFFFFFFFu, se, o);
    float l = mx + logf(se);
    out[(size_t)node * D2V + lane]      = v0 - l;
    out[(size_t)node * D2V + 32 + lane] = v1 - l;
}

// ---------------- host launch ----------------
extern "C" void kernel_launch(void* const* d_in, const int* in_sizes, int n_in,
                              void* d_out, int out_size) {
    const float* x        = (const float*)d_in[0];
    const void*  ei       = d_in[1];
    const float* W1       = (const float*)d_in[2];
    const float* att_src1 = (const float*)d_in[3];
    const float* att_dst1 = (const float*)d_in[4];
    const float* b1       = (const float*)d_in[5];
    const float* W2       = (const float*)d_in[6];
    const float* att_src2 = (const float*)d_in[7];
    const float* att_dst2 = (const float*)d_in[8];
    const float* b2       = (const float*)d_in[9];
    float* out = (float*)d_out;

    float *h1, *agg1, *h2, *agg2, *as1, *ad1, *m1, *s1, *as2, *ad2, *m2, *s2, *ex1, *ex2;
    cudaGetSymbolAddress((void**)&h1,   g_h1);
    cudaGetSymbolAddress((void**)&agg1, g_agg1);
    cudaGetSymbolAddress((void**)&h2,   g_h2);
    cudaGetSymbolAddress((void**)&agg2, g_agg2);
    cudaGetSymbolAddress((void**)&as1,  g_as1);
    cudaGetSymbolAddress((void**)&ad1,  g_ad1);
    cudaGetSymbolAddress((void**)&m1,   g_m1);
    cudaGetSymbolAddress((void**)&s1,   g_s1);
    cudaGetSymbolAddress((void**)&as2,  g_as2);
    cudaGetSymbolAddress((void**)&ad2,  g_ad2);
    cudaGetSymbolAddress((void**)&m2,   g_m2);
    cudaGetSymbolAddress((void**)&s2,   g_s2);
    cudaGetSymbolAddress((void**)&ex1,  g_ex1);
    cudaGetSymbolAddress((void**)&ex2,  g_ex2);

    // edge-index normalization (handles int32 or int64 delivery)
    detect_kernel<<<1, 1>>>(ei);
    convert_kernel<<<(2 * NE + 255) / 256, 256>>>(ei);

    // reset accumulators (device globals persist across graph replays)
    cudaMemsetAsync(agg1, 0, sizeof(float) * (size_t)NN * D1V);
    cudaMemsetAsync(agg2, 0, sizeof(float) * (size_t)NN * D2V);
    init_kernel<<<(NN * H1V + 255) / 256, 256>>>();

    // ---- layer 1 ----
    sgemm_kernel<128, 128, 8, 8, 8>
        <<<dim3((NN + 127) / 128, D1V / 128), dim3(16, 16)>>>(x, W1, h1, NN, D1V, FIN);
    dots_kernel<<<(NN * H1V + 255) / 256, 256>>>(h1, att_src1, att_dst1, as1, ad1, H1V, C1V);
    edge_max_kernel<H1V><<<(NEP + 255) / 256, 256>>>(as1, ad1, m1);
    edge_exp_kernel<H1V><<<(NEP + 255) / 256, 256>>>(as1, ad1, m1, ex1, s1);
    edge_agg_kernel<H1V, C1V><<<(NEP + 7) / 8, 256>>>(h1, ex1, s1, agg1);
    relu_bias_kernel<<<(int)(((size_t)NN * D1V + 255) / 256), 256>>>(b1);

    // ---- layer 2 ----
    sgemm_kernel<128, 64, 8, 8, 4>
        <<<dim3((NN + 127) / 128, 1), dim3(16, 16)>>>(agg1, W2, h2, NN, D2V, D1V);
    dots_kernel<<<(NN + 255) / 256, 256>>>(h2, att_src2, att_dst2, as2, ad2, 1, D2V);
    edge_max_kernel<1><<<(NEP + 255) / 256, 256>>>(as2, ad2, m2);
    edge_exp_kernel<1><<<(NEP + 255) / 256, 256>>>(as2, ad2, m2, ex2, s2);
    edge_agg_kernel<1, D2V><<<(NEP + 7) / 8, 256>>>(h2, ex2, s2, agg2);

    logsoftmax_kernel<<<(NN + 7) / 8, 256>>>(b2, out);
}

// round 9
// speedup vs baseline: 2.6962x; 2.6962x over previous
#include <cuda_runtime.h>
#include <math.h>

#define NN   50000
#define NE   800000
#define NEP  850000          // NE + NN self loops
#define FIN  512
#define H1V  8
#define C1V  32
#define D1V  256             // H1V*C1V
#define D2V  64
#define NEG_SLOPE 0.2f
#define EPS_SM 1e-16f
#define NEGBIG (-1e30f)
#define SCAN_CHUNK 512
#define NB ((NN + SCAN_CHUNK - 1) / SCAN_CHUNK)   // 98

// ---------------- scratch (device globals; no allocs) ----------------
__device__ int   g_flag;                       // 1 = edge_index is int64
__device__ int   g_src[NE];
__device__ int   g_dst[NE];
__device__ int   g_deg[NN];
__device__ int   g_rowptr[NN];
__device__ int   g_cursor[NN];
__device__ int   g_bsum[128];
__device__ int   g_bofs[128];
__device__ int   g_csrc[NEP];                  // CSR: src node per slot, bucketed by dst
__device__ float g_h1[(size_t)NN * D1V];       // x@W1
__device__ float g_agg1[(size_t)NN * D1V];     // layer1 out (bias+relu fused)
__device__ float g_h2[(size_t)NN * D2V];       // agg1@W2
__device__ float g_as1[NN * H1V], g_ad1[NN * H1V], g_m1[NN * H1V], g_s1[NN * H1V];
__device__ float g_as2[NN],       g_ad2[NN],       g_m2[NN],       g_s2[NN];

// ---------------- helpers ----------------
__device__ __forceinline__ float lrelu(float v) { return v > 0.f ? v : NEG_SLOPE * v; }

// ---------------- edge-index width detection & normalization ----------------
__global__ void detect_kernel(const void* ei) {
    const long long* p = (const long long*)ei;
    int ok = 1;
    for (int i = 0; i < 64; i++) {
        long long v = p[i];
        if (v < 0 || v >= NN) { ok = 0; break; }
    }
    g_flag = ok;
}

__global__ void convert_kernel(const void* ei) {
    int i = blockIdx.x * blockDim.x + threadIdx.x;
    if (i >= 2 * NE) return;
    int v = g_flag ? (int)((const long long*)ei)[i] : ((const int*)ei)[i];
    if (i < NE) g_src[i] = v;
    else        g_dst[i - NE] = v;
}

// ---------------- CSR build: histogram -> scan -> scatter ----------------
__global__ void hist_kernel() {
    int e = blockIdx.x * blockDim.x + threadIdx.x;
    if (e >= NEP) return;
    int d = (e < NE) ? g_dst[e] : (e - NE);
    atomicAdd(&g_deg[d], 1);
}

__global__ void scan1_kernel() {       // per-chunk exclusive scan (512 threads)
    __shared__ int sh[SCAN_CHUNK];
    int tid = threadIdx.x;
    int i = blockIdx.x * SCAN_CHUNK + tid;
    int v = (i < NN) ? g_deg[i] : 0;
    sh[tid] = v;
    __syncthreads();
#pragma unroll
    for (int o = 1; o < SCAN_CHUNK; o <<= 1) {
        int t = (tid >= o) ? sh[tid - o] : 0;
        __syncthreads();
        sh[tid] += t;
        __syncthreads();
    }
    if (i < NN) g_rowptr[i] = sh[tid] - v;          // local exclusive
    if (tid == SCAN_CHUNK - 1) g_bsum[blockIdx.x] = sh[tid];
}

__global__ void scan2_kernel() {       // scan of 98 block sums (128 threads)
    __shared__ int sh[128];
    int tid = threadIdx.x;
    int v = (tid < NB) ? g_bsum[tid] : 0;
    sh[tid] = v;
    __syncthreads();
#pragma unroll
    for (int o = 1; o < 128; o <<= 1) {
        int t = (tid >= o) ? sh[tid - o] : 0;
        __syncthreads();
        sh[tid] += t;
        __syncthreads();
    }
    if (tid < NB) g_bofs[tid] = sh[tid] - v;        // exclusive block offsets
}

__global__ void scan3_kernel() {
    int i = blockIdx.x * blockDim.x + threadIdx.x;
    if (i >= NN) return;
    int r = g_rowptr[i] + g_bofs[i / SCAN_CHUNK];
    g_rowptr[i] = r;
    g_cursor[i] = r;
}

__global__ void scatter_kernel() {
    int e = blockIdx.x * blockDim.x + threadIdx.x;
    if (e >= NEP) return;
    int s, d;
    if (e < NE) { s = g_src[e]; d = g_dst[e]; }
    else        { s = d = e - NE; }
    int slot = atomicAdd(&g_cursor[d], 1);
    g_csrc[slot] = s;
}

// ---------------- register-tiled SGEMM: C[M,Nn] = A[M,K] @ B[K,Nn] ----------------
template<int BM, int BN, int BK, int TM, int TN>
__global__ void __launch_bounds__(256)
sgemm_kernel(const float* __restrict__ A, const float* __restrict__ B,
             float* __restrict__ C, int M, int Nn, int K) {
    constexpr int THREADS = (BM / TM) * (BN / TN);
    __shared__ float As[BK][BM];
    __shared__ float Bs[BK][BN];
    const int tid = threadIdx.y * blockDim.x + threadIdx.x;
    const int m0 = blockIdx.x * BM;
    const int n0 = blockIdx.y * BN;

    float acc[TM][TN];
#pragma unroll
    for (int i = 0; i < TM; i++)
#pragma unroll
        for (int j = 0; j < TN; j++) acc[i][j] = 0.0f;

    for (int k0 = 0; k0 < K; k0 += BK) {
#pragma unroll
        for (int t = tid; t < BM * BK / 4; t += THREADS) {
            int row = t / (BK / 4);
            int q   = t % (BK / 4);
            float4 v = make_float4(0.f, 0.f, 0.f, 0.f);
            if (m0 + row < M)
                v = *reinterpret_cast<const float4*>(&A[(size_t)(m0 + row) * K + k0 + q * 4]);
            As[q * 4 + 0][row] = v.x;
            As[q * 4 + 1][row] = v.y;
            As[q * 4 + 2][row] = v.z;
            As[q * 4 + 3][row] = v.w;
        }
#pragma unroll
        for (int t = tid; t < BK * BN / 4; t += THREADS) {
            int row = t / (BN / 4);
            int col = t % (BN / 4);
            float4 v = *reinterpret_cast<const float4*>(&B[(size_t)(k0 + row) * Nn + n0 + col * 4]);
            *reinterpret_cast<float4*>(&Bs[row][col * 4]) = v;
        }
        __syncthreads();

#pragma unroll
        for (int k = 0; k < BK; k++) {
            float ra[TM], rb[TN];
#pragma unroll
            for (int i = 0; i < TM; i++) ra[i] = As[k][threadIdx.y * TM + i];
#pragma unroll
            for (int j = 0; j < TN; j++) rb[j] = Bs[k][threadIdx.x * TN + j];
#pragma unroll
            for (int i = 0; i < TM; i++)
#pragma unroll
                for (int j = 0; j < TN; j++) acc[i][j] += ra[i] * rb[j];
        }
        __syncthreads();
    }

#pragma unroll
    for (int i = 0; i < TM; i++) {
        int r = m0 + threadIdx.y * TM + i;
        if (r < M) {
#pragma unroll
            for (int j = 0; j < TN; j++)
                C[(size_t)r * Nn + n0 + threadIdx.x * TN + j] = acc[i][j];
        }
    }
}

// ---------------- per-node attention dot products ----------------
__global__ void dots_kernel(const float* __restrict__ h, const float* __restrict__ av_s,
                            const float* __restrict__ av_d, float* __restrict__ oas,
                            float* __restrict__ oad, int heads, int c) {
    int i = blockIdx.x * blockDim.x + threadIdx.x;   // i = node*heads + head
    if (i >= NN * heads) return;
    int hd = i % heads;
    const float* row = h + (size_t)i * c;
    float x1 = 0.f, x2 = 0.f;
    for (int j = 0; j < c; j += 4) {
        float4 v = __ldg((const float4*)(row + j));
        float4 a = __ldg((const float4*)(av_s + hd * c + j));
        float4 b = __ldg((const float4*)(av_d + hd * c + j));
        x1 += v.x * a.x + v.y * a.y + v.z * a.z + v.w * a.w;
        x2 += v.x * b.x + v.y * b.y + v.z * b.z + v.w * b.w;
    }
    oas[i] = x1;
    oad[i] = x2;
}

// ---------------- layer 1: fused max+sum (online softmax), warp per dst ----------------
// lane = eidx*8 + head: 4 edges in flight x 8 heads
__global__ void __launch_bounds__(256)
pass_ab1_kernel(const float* __restrict__ oas, const float* __restrict__ oad) {
    int d = (blockIdx.x * blockDim.x + threadIdx.x) >> 5;
    if (d >= NN) return;
    int lane = threadIdx.x & 31;
    int eidx = lane >> 3, h = lane & 7;
    int off = g_rowptr[d], deg = g_deg[d];
    float adh = __ldg(&oad[d * 8 + h]);
    float m_run = NEGBIG, s_run = 0.f;
    for (int i = eidx; i < deg; i += 4) {
        int s = __ldg(&g_csrc[off + i]);
        float v = lrelu(__ldg(&oas[s * 8 + h]) + adh);
        float mnew = fmaxf(m_run, v);
        s_run = s_run * __expf(m_run - mnew) + __expf(v - mnew);
        m_run = mnew;
    }
#pragma unroll
    for (int o = 8; o <= 16; o <<= 1) {
        float mo = __shfl_xor_sync(0xFFFFFFFFu, m_run, o);
        float so = __shfl_xor_sync(0xFFFFFFFFu, s_run, o);
        float mnew = fmaxf(m_run, mo);
        s_run = s_run * __expf(m_run - mnew) + so * __expf(mo - mnew);
        m_run = mnew;
    }
    if (eidx == 0) {
        g_m1[d * 8 + h] = m_run;
        g_s1[d * 8 + h] = s_run;
    }
}

// ---------------- layer 1: aggregation + bias + relu, warp per dst ----------------
// lane owns 8 contiguous channels (one head per lane group of 4)
__global__ void __launch_bounds__(256)
pass_c1_kernel(const float* __restrict__ oas, const float* __restrict__ oad,
               const float* __restrict__ b) {
    int d = (blockIdx.x * blockDim.x + threadIdx.x) >> 5;
    if (d >= NN) return;
    int lane = threadIdx.x & 31;
    int base = lane * 8;
    int h = lane >> 2;
    int off = g_rowptr[d], deg = g_deg[d];
    float mh  = __ldg(&g_m1[d * 8 + h]);
    float inv = 1.f / (__ldg(&g_s1[d * 8 + h]) + EPS_SM);
    float adh = __ldg(&oad[d * 8 + h]);
    float acc[8];
#pragma unroll
    for (int j = 0; j < 8; j++) acc[j] = 0.f;
    int s_cur = (deg > 0) ? __ldg(&g_csrc[off]) : 0;
    for (int i = 0; i < deg; i++) {
        int s_nxt = (i + 1 < deg) ? __ldg(&g_csrc[off + i + 1]) : 0;   // prefetch
        float v = lrelu(__ldg(&oas[s_cur * 8 + h]) + adh);
        float ex = __expf(v - mh) * inv;
        const float* sp = g_h1 + (size_t)s_cur * D1V + base;
        float4 a0 = __ldg((const float4*)sp);
        float4 a1 = __ldg((const float4*)(sp + 4));
        acc[0] += a0.x * ex; acc[1] += a0.y * ex; acc[2] += a0.z * ex; acc[3] += a0.w * ex;
        acc[4] += a1.x * ex; acc[5] += a1.y * ex; acc[6] += a1.z * ex; acc[7] += a1.w * ex;
        s_cur = s_nxt;
    }
    float4 bb0 = __ldg((const float4*)(b + base));
    float4 bb1 = __ldg((const float4*)(b + base + 4));
    float4 o0, o1;
    o0.x = fmaxf(acc[0] + bb0.x, 0.f); o0.y = fmaxf(acc[1] + bb0.y, 0.f);
    o0.z = fmaxf(acc[2] + bb0.z, 0.f); o0.w = fmaxf(acc[3] + bb0.w, 0.f);
    o1.x = fmaxf(acc[4] + bb1.x, 0.f); o1.y = fmaxf(acc[5] + bb1.y, 0.f);
    o1.z = fmaxf(acc[6] + bb1.z, 0.f); o1.w = fmaxf(acc[7] + bb1.w, 0.f);
    float* op = g_agg1 + (size_t)d * D1V + base;
    *(float4*)op       = o0;
    *(float4*)(op + 4) = o1;
}

// ---------------- layer 2: fused max+sum, warp per dst (HEADS=1) ----------------
__global__ void __launch_bounds__(256)
pass_ab2_kernel(const float* __restrict__ oas, const float* __restrict__ oad) {
    int d = (blockIdx.x * blockDim.x + threadIdx.x) >> 5;
    if (d >= NN) return;
    int lane = threadIdx.x & 31;
    int off = g_rowptr[d], deg = g_deg[d];
    float add = __ldg(&oad[d]);
    float m_run = NEGBIG, s_run = 0.f;
    for (int i = lane; i < deg; i += 32) {
        int s = __ldg(&g_csrc[off + i]);
        float v = lrelu(__ldg(&oas[s]) + add);
        float mnew = fmaxf(m_run, v);
        s_run = s_run * __expf(m_run - mnew) + __expf(v - mnew);
        m_run = mnew;
    }
#pragma unroll
    for (int o = 1; o <= 16; o <<= 1) {
        float mo = __shfl_xor_sync(0xFFFFFFFFu, m_run, o);
        float so = __shfl_xor_sync(0xFFFFFFFFu, s_run, o);
        float mnew = fmaxf(m_run, mo);
        s_run = s_run * __expf(m_run - mnew) + so * __expf(mo - mnew);
        m_run = mnew;
    }
    if (lane == 0) {
        g_m2[d] = m_run;
        g_s2[d] = s_run;
    }
}

// ---------------- layer 2: aggregation + bias + log_softmax, warp per dst ----------------
__global__ void __launch_bounds__(256)
pass_c2_kernel(const float* __restrict__ oas, const float* __restrict__ oad,
               const float* __restrict__ b, float* __restrict__ out) {
    int d = (blockIdx.x * blockDim.x + threadIdx.x) >> 5;
    if (d >= NN) return;
    int lane = threadIdx.x & 31;
    int c0 = lane * 2;
    int off = g_rowptr[d], deg = g_deg[d];
    float mh  = __ldg(&g_m2[d]);
    float inv = 1.f / (__ldg(&g_s2[d]) + EPS_SM);
    float add = __ldg(&oad[d]);
    float acc0 = 0.f, acc1 = 0.f;
    int s_cur = (deg > 0) ? __ldg(&g_csrc[off]) : 0;
    for (int i = 0; i < deg; i++) {
        int s_nxt = (i + 1 < deg) ? __ldg(&g_csrc[off + i + 1]) : 0;   // prefetch
        float v = lrelu(__ldg(&oas[s_cur]) + add);
        float ex = __expf(v - mh) * inv;
        float2 hv = __ldg((const float2*)(g_h2 + (size_t)s_cur * D2V + c0));
        acc0 += hv.x * ex;
        acc1 += hv.y * ex;
        s_cur = s_nxt;
    }
    float v0 = acc0 + __ldg(&b[c0]);
    float v1 = acc1 + __ldg(&b[c0 + 1]);
    float mx = fmaxf(v0, v1);
#pragma unroll
    for (int o = 16; o; o >>= 1) mx = fmaxf(mx, __shfl_xor_sync(0xFFFFFFFFu, mx, o));
    float se = __expf(v0 - mx) + __expf(v1 - mx);
#pragma unroll
    for (int o = 16; o; o >>= 1) se += __shfl_xor_sync(0xFFFFFFFFu, se, o);
    float l = mx + logf(se);
    out[(size_t)d * D2V + c0]     = v0 - l;
    out[(size_t)d * D2V + c0 + 1] = v1 - l;
}

// ---------------- host launch ----------------
extern "C" void kernel_launch(void* const* d_in, const int* in_sizes, int n_in,
                              void* d_out, int out_size) {
    const float* x        = (const float*)d_in[0];
    const void*  ei       = d_in[1];
    const float* W1       = (const float*)d_in[2];
    const float* att_src1 = (const float*)d_in[3];
    const float* att_dst1 = (const float*)d_in[4];
    const float* b1       = (const float*)d_in[5];
    const float* W2       = (const float*)d_in[6];
    const float* att_src2 = (const float*)d_in[7];
    const float* att_dst2 = (const float*)d_in[8];
    const float* b2       = (const float*)d_in[9];
    float* out = (float*)d_out;

    float *h1, *agg1, *h2, *as1, *ad1, *as2, *ad2;
    int *degp;
    cudaGetSymbolAddress((void**)&h1,   g_h1);
    cudaGetSymbolAddress((void**)&agg1, g_agg1);
    cudaGetSymbolAddress((void**)&h2,   g_h2);
    cudaGetSymbolAddress((void**)&as1,  g_as1);
    cudaGetSymbolAddress((void**)&ad1,  g_ad1);
    cudaGetSymbolAddress((void**)&as2,  g_as2);
    cudaGetSymbolAddress((void**)&ad2,  g_ad2);
    cudaGetSymbolAddress((void**)&degp, g_deg);

    // edge-index normalization (handles int32 or int64 delivery)
    detect_kernel<<<1, 1>>>(ei);
    convert_kernel<<<(2 * NE + 255) / 256, 256>>>(ei);

    // CSR build (re-done every launch; deterministic set, order-free math downstream)
    cudaMemsetAsync(degp, 0, sizeof(int) * NN);
    hist_kernel<<<(NEP + 255) / 256, 256>>>();
    scan1_kernel<<<NB, SCAN_CHUNK>>>();
    scan2_kernel<<<1, 128>>>();
    scan3_kernel<<<(NN + 255) / 256, 256>>>();
    scatter_kernel<<<(NEP + 255) / 256, 256>>>();

    const int WG = (NN * 32 + 255) / 256;   // warp-per-dst grids

    // ---- layer 1 ----
    sgemm_kernel<128, 128, 16, 8, 8>
        <<<dim3((NN + 127) / 128, D1V / 128), dim3(16, 16)>>>(x, W1, h1, NN, D1V, FIN);
    dots_kernel<<<(NN * H1V + 255) / 256, 256>>>(h1, att_src1, att_dst1, as1, ad1, H1V, C1V);
    pass_ab1_kernel<<<WG, 256>>>(as1, ad1);
    pass_c1_kernel<<<WG, 256>>>(as1, ad1, b1);

    // ---- layer 2 ----
    sgemm_kernel<128, 64, 16, 8, 4>
        <<<dim3((NN + 127) / 128, 1), dim3(16, 16)>>>(agg1, W2, h2, NN, D2V, D1V);
    dots_kernel<<<(NN + 255) / 256, 256>>>(h2, att_src2, att_dst2, as2, ad2, 1, D2V);
    pass_ab2_kernel<<<WG, 256>>>(as2, ad2);
    pass_c2_kernel<<<WG, 256>>>(as2, ad2, b2, out);
}

// round 14
// speedup vs baseline: 4.5100x; 1.6727x over previous
#include <cuda_runtime.h>
#include <math.h>
#include <stdint.h>

#define NN   50000
#define NE   800000
#define NEP  850000          // NE + NN self loops
#define FIN  512
#define H1V  8
#define C1V  32
#define D1V  256             // H1V*C1V
#define D2V  64
#define NEG_SLOPE 0.2f
#define EPS_SM 1e-16f
#define NEGBIG (-1e30f)
#define SCAN_CHUNK 512
#define NB ((NN + SCAN_CHUNK - 1) / SCAN_CHUNK)   // 98

// ---------------- scratch (device globals; no allocs) ----------------
__device__ int   g_flag;                       // 1 = edge_index is int64
__device__ int   g_src[NE];
__device__ int   g_dst[NE];
__device__ int   g_deg[NN];
__device__ int   g_rowptr[NN];
__device__ int   g_cursor[NN];
__device__ int   g_bsum[128];
__device__ int   g_bofs[128];
__device__ int   g_csrc[NEP];                  // CSR: src node per slot, bucketed by dst
__device__ float g_h1[(size_t)NN * D1V];       // x@W1
__device__ float g_agg1[(size_t)NN * D1V];     // layer1 out (bias+relu fused)
__device__ float g_h2[(size_t)NN * D2V];       // agg1@W2
__device__ float g_as1[NN * H1V], g_ad1[NN * H1V], g_m1[NN * H1V], g_s1[NN * H1V];
__device__ float g_as2[NN],       g_ad2[NN],       g_m2[NN],       g_s2[NN];

// ---------------- helpers ----------------
__device__ __forceinline__ float lrelu(float v) { return v > 0.f ? v : NEG_SLOPE * v; }

__device__ __forceinline__ uint32_t f2tf32(float f) {
    uint32_t u;
    asm("cvt.rna.tf32.f32 %0, %1;" : "=r"(u) : "f"(f));
    return u;
}

// ---------------- edge-index width detection & normalization ----------------
__global__ void detect_kernel(const void* ei) {
    const long long* p = (const long long*)ei;
    int ok = 1;
    for (int i = 0; i < 64; i++) {
        long long v = p[i];
        if (v < 0 || v >= NN) { ok = 0; break; }
    }
    g_flag = ok;
}

__global__ void convert_kernel(const void* ei) {
    int i = blockIdx.x * blockDim.x + threadIdx.x;
    if (i >= 2 * NE) return;
    int v = g_flag ? (int)((const long long*)ei)[i] : ((const int*)ei)[i];
    if (i < NE) g_src[i] = v;
    else        g_dst[i - NE] = v;
}

// ---------------- CSR build: histogram -> scan -> scatter ----------------
__global__ void hist_kernel() {
    int e = blockIdx.x * blockDim.x + threadIdx.x;
    if (e >= NEP) return;
    int d = (e < NE) ? g_dst[e] : (e - NE);
    atomicAdd(&g_deg[d], 1);
}

__global__ void scan1_kernel() {       // per-chunk exclusive scan (512 threads)
    __shared__ int sh[SCAN_CHUNK];
    int tid = threadIdx.x;
    int i = blockIdx.x * SCAN_CHUNK + tid;
    int v = (i < NN) ? g_deg[i] : 0;
    sh[tid] = v;
    __syncthreads();
#pragma unroll
    for (int o = 1; o < SCAN_CHUNK; o <<= 1) {
        int t = (tid >= o) ? sh[tid - o] : 0;
        __syncthreads();
        sh[tid] += t;
        __syncthreads();
    }
    if (i < NN) g_rowptr[i] = sh[tid] - v;          // local exclusive
    if (tid == SCAN_CHUNK - 1) g_bsum[blockIdx.x] = sh[tid];
}

__global__ void scan2_kernel() {       // scan of 98 block sums (128 threads)
    __shared__ int sh[128];
    int tid = threadIdx.x;
    int v = (tid < NB) ? g_bsum[tid] : 0;
    sh[tid] = v;
    __syncthreads();
#pragma unroll
    for (int o = 1; o < 128; o <<= 1) {
        int t = (tid >= o) ? sh[tid - o] : 0;
        __syncthreads();
        sh[tid] += t;
        __syncthreads();
    }
    if (tid < NB) g_bofs[tid] = sh[tid] - v;        // exclusive block offsets
}

__global__ void scan3_kernel() {
    int i = blockIdx.x * blockDim.x + threadIdx.x;
    if (i >= NN) return;
    int r = g_rowptr[i] + g_bofs[i / SCAN_CHUNK];
    g_rowptr[i] = r;
    g_cursor[i] = r;
}

__global__ void scatter_kernel() {
    int e = blockIdx.x * blockDim.x + threadIdx.x;
    if (e >= NEP) return;
    int s, d;
    if (e < NE) { s = g_src[e]; d = g_dst[e]; }
    else        { s = d = e - NE; }
    int slot = atomicAdd(&g_cursor[d], 1);
    g_csrc[slot] = s;
}

// ---------------- tf32 tensor-core GEMM: C[M,256] = A[M,512] @ B[512,256] ----------------
// 128x128x32 block tile, 8 warps, warp = 32x64 (2x8 grid of m16n8k8 mma)
#define GBM 128
#define GBN 128
#define GBK 32
#define APAD 4    // As stride 36: a-frag bank = (4*row + k) % 32, conflict-free
#define BPAD 8    // Bs stride 136: b-frag bank = (8*k + n) % 32, conflict-free

__global__ void __launch_bounds__(256)
tf32_gemm_kernel(const float* __restrict__ A, const float* __restrict__ B,
                 float* __restrict__ C, int M, int Nn, int K) {
    __shared__ uint32_t As[GBM][GBK + APAD];
    __shared__ uint32_t Bs[GBK][GBN + BPAD];

    const int tid  = threadIdx.x;
    const int lane = tid & 31;
    const int wid  = tid >> 5;
    const int g    = lane >> 2;     // groupID 0..7
    const int tg   = lane & 3;      // threadID_in_group 0..3
    const int wm   = (wid & 3) * 32;   // warp m-offset in tile
    const int wn   = (wid >> 2) * 64;  // warp n-offset in tile
    const int m0   = blockIdx.x * GBM;
    const int n0   = blockIdx.y * GBN;

    float c[2][8][4];
#pragma unroll
    for (int mt = 0; mt < 2; mt++)
#pragma unroll
        for (int nt = 0; nt < 8; nt++)
#pragma unroll
            for (int r = 0; r < 4; r++) c[mt][nt][r] = 0.f;

    for (int k0 = 0; k0 < K; k0 += GBK) {
        // A tile: 128x32 = 1024 float4, 4 per thread
#pragma unroll
        for (int i = 0; i < 4; i++) {
            int t = tid + i * 256;
            int row = t >> 3;            // /8 float4 per row
            int q   = (t & 7) * 4;
            float4 v = make_float4(0.f, 0.f, 0.f, 0.f);
            if (m0 + row < M)
                v = *reinterpret_cast<const float4*>(&A[(size_t)(m0 + row) * K + k0 + q]);
            As[row][q + 0] = f2tf32(v.x);
            As[row][q + 1] = f2tf32(v.y);
            As[row][q + 2] = f2tf32(v.z);
            As[row][q + 3] = f2tf32(v.w);
        }
        // B tile: 32x128 = 1024 float4, 4 per thread
#pragma unroll
        for (int i = 0; i < 4; i++) {
            int t = tid + i * 256;
            int row = t >> 5;            // /32 float4 per row
            int q   = (t & 31) * 4;
            float4 v = *reinterpret_cast<const float4*>(&B[(size_t)(k0 + row) * Nn + n0 + q]);
            Bs[row][q + 0] = f2tf32(v.x);
            Bs[row][q + 1] = f2tf32(v.y);
            Bs[row][q + 2] = f2tf32(v.z);
            Bs[row][q + 3] = f2tf32(v.w);
        }
        __syncthreads();

#pragma unroll
        for (int ks = 0; ks < GBK; ks += 8) {
            uint32_t af[2][4], bf[8][2];
#pragma unroll
            for (int mt = 0; mt < 2; mt++) {
                int r = wm + mt * 16 + g;
                af[mt][0] = As[r][ks + tg];
                af[mt][1] = As[r + 8][ks + tg];
                af[mt][2] = As[r][ks + tg + 4];
                af[mt][3] = As[r + 8][ks + tg + 4];
            }
#pragma unroll
            for (int nt = 0; nt < 8; nt++) {
                int n = wn + nt * 8 + g;
                bf[nt][0] = Bs[ks + tg][n];
                bf[nt][1] = Bs[ks + tg + 4][n];
            }
#pragma unroll
            for (int mt = 0; mt < 2; mt++)
#pragma unroll
                for (int nt = 0; nt < 8; nt++) {
                    asm volatile(
                        "mma.sync.aligned.m16n8k8.row.col.f32.tf32.tf32.f32 "
                        "{%0,%1,%2,%3}, {%4,%5,%6,%7}, {%8,%9}, {%0,%1,%2,%3};"
                        : "+f"(c[mt][nt][0]), "+f"(c[mt][nt][1]),
                          "+f"(c[mt][nt][2]), "+f"(c[mt][nt][3])
                        : "r"(af[mt][0]), "r"(af[mt][1]), "r"(af[mt][2]), "r"(af[mt][3]),
                          "r"(bf[nt][0]), "r"(bf[nt][1]));
                }
        }
        __syncthreads();
    }

    // store: c0,c1 -> (row, 2tg), c2,c3 -> (row+8, 2tg)
#pragma unroll
    for (int mt = 0; mt < 2; mt++) {
#pragma unroll
        for (int nt = 0; nt < 8; nt++) {
            int col = n0 + wn + nt * 8 + tg * 2;
            int r0  = m0 + wm + mt * 16 + g;
            if (r0 < M)
                *reinterpret_cast<float2*>(&C[(size_t)r0 * Nn + col]) =
                    make_float2(c[mt][nt][0], c[mt][nt][1]);
            if (r0 + 8 < M)
                *reinterpret_cast<float2*>(&C[(size_t)(r0 + 8) * Nn + col]) =
                    make_float2(c[mt][nt][2], c[mt][nt][3]);
        }
    }
}

// ---------------- register-tiled SGEMM (fp32, layer 2): C[M,Nn] = A[M,K] @ B[K,Nn] ----------------
template<int BM, int BN, int BK, int TM, int TN>
__global__ void __launch_bounds__(256)
sgemm_kernel(const float* __restrict__ A, const float* __restrict__ B,
             float* __restrict__ C, int M, int Nn, int K) {
    constexpr int THREADS = (BM / TM) * (BN / TN);
    __shared__ float As[BK][BM];
    __shared__ float Bs[BK][BN];
    const int tid = threadIdx.y * blockDim.x + threadIdx.x;
    const int m0 = blockIdx.x * BM;
    const int n0 = blockIdx.y * BN;

    float acc[TM][TN];
#pragma unroll
    for (int i = 0; i < TM; i++)
#pragma unroll
        for (int j = 0; j < TN; j++) acc[i][j] = 0.0f;

    for (int k0 = 0; k0 < K; k0 += BK) {
#pragma unroll
        for (int t = tid; t < BM * BK / 4; t += THREADS) {
            int row = t / (BK / 4);
            int q   = t % (BK / 4);
            float4 v = make_float4(0.f, 0.f, 0.f, 0.f);
            if (m0 + row < M)
                v = *reinterpret_cast<const float4*>(&A[(size_t)(m0 + row) * K + k0 + q * 4]);
            As[q * 4 + 0][row] = v.x;
            As[q * 4 + 1][row] = v.y;
            As[q * 4 + 2][row] = v.z;
            As[q * 4 + 3][row] = v.w;
        }
#pragma unroll
        for (int t = tid; t < BK * BN / 4; t += THREADS) {
            int row = t / (BN / 4);
            int col = t % (BN / 4);
            float4 v = *reinterpret_cast<const float4*>(&B[(size_t)(k0 + row) * Nn + n0 + col * 4]);
            *reinterpret_cast<float4*>(&Bs[row][col * 4]) = v;
        }
        __syncthreads();

#pragma unroll
        for (int k = 0; k < BK; k++) {
            float ra[TM], rb[TN];
#pragma unroll
            for (int i = 0; i < TM; i++) ra[i] = As[k][threadIdx.y * TM + i];
#pragma unroll
            for (int j = 0; j < TN; j++) rb[j] = Bs[k][threadIdx.x * TN + j];
#pragma unroll
            for (int i = 0; i < TM; i++)
#pragma unroll
                for (int j = 0; j < TN; j++) acc[i][j] += ra[i] * rb[j];
        }
        __syncthreads();
    }

#pragma unroll
    for (int i = 0; i < TM; i++) {
        int r = m0 + threadIdx.y * TM + i;
        if (r < M) {
#pragma unroll
            for (int j = 0; j < TN; j++)
                C[(size_t)r * Nn + n0 + threadIdx.x * TN + j] = acc[i][j];
        }
    }
}

// ---------------- per-node attention dot products ----------------
__global__ void dots_kernel(const float* __restrict__ h, const float* __restrict__ av_s,
                            const float* __restrict__ av_d, float* __restrict__ oas,
                            float* __restrict__ oad, int heads, int c) {
    int i = blockIdx.x * blockDim.x + threadIdx.x;   // i = node*heads + head
    if (i >= NN * heads) return;
    int hd = i % heads;
    const float* row = h + (size_t)i * c;
    float x1 = 0.f, x2 = 0.f;
    for (int j = 0; j < c; j += 4) {
        float4 v = __ldg((const float4*)(row + j));
        float4 a = __ldg((const float4*)(av_s + hd * c + j));
        float4 b = __ldg((const float4*)(av_d + hd * c + j));
        x1 += v.x * a.x + v.y * a.y + v.z * a.z + v.w * a.w;
        x2 += v.x * b.x + v.y * b.y + v.z * b.z + v.w * b.w;
    }
    oas[i] = x1;
    oad[i] = x2;
}

// ---------------- layer 1: fused max+sum (online softmax), warp per dst ----------------
__global__ void __launch_bounds__(256)
pass_ab1_kernel(const float* __restrict__ oas, const float* __restrict__ oad) {
    int d = (blockIdx.x * blockDim.x + threadIdx.x) >> 5;
    if (d >= NN) return;
    int lane = threadIdx.x & 31;
    int eidx = lane >> 3, h = lane & 7;
    int off = g_rowptr[d], deg = g_deg[d];
    float adh = __ldg(&oad[d * 8 + h]);
    float m_run = NEGBIG, s_run = 0.f;
    for (int i = eidx; i < deg; i += 4) {
        int s = __ldg(&g_csrc[off + i]);
        float v = lrelu(__ldg(&oas[s * 8 + h]) + adh);
        float mnew = fmaxf(m_run, v);
        s_run = s_run * __expf(m_run - mnew) + __expf(v - mnew);
        m_run = mnew;
    }
#pragma unroll
    for (int o = 8; o <= 16; o <<= 1) {
        float mo = __shfl_xor_sync(0xFFFFFFFFu, m_run, o);
        float so = __shfl_xor_sync(0xFFFFFFFFu, s_run, o);
        float mnew = fmaxf(m_run, mo);
        s_run = s_run * __expf(m_run - mnew) + so * __expf(mo - mnew);
        m_run = mnew;
    }
    if (eidx == 0) {
        g_m1[d * 8 + h] = m_run;
        g_s1[d * 8 + h] = s_run;
    }
}

// ---------------- layer 1: aggregation + bias + relu, warp per dst ----------------
__global__ void __launch_bounds__(256)
pass_c1_kernel(const float* __restrict__ oas, const float* __restrict__ oad,
               const float* __restrict__ b) {
    int d = (blockIdx.x * blockDim.x + threadIdx.x) >> 5;
    if (d >= NN) return;
    int lane = threadIdx.x & 31;
    int base = lane * 8;
    int h = lane >> 2;
    int off = g_rowptr[d], deg = g_deg[d];
    float mh  = __ldg(&g_m1[d * 8 + h]);
    float inv = 1.f / (__ldg(&g_s1[d * 8 + h]) + EPS_SM);
    float adh = __ldg(&oad[d * 8 + h]);
    float acc[8];
#pragma unroll
    for (int j = 0; j < 8; j++) acc[j] = 0.f;
    int s_cur = (deg > 0) ? __ldg(&g_csrc[off]) : 0;
    for (int i = 0; i < deg; i++) {
        int s_nxt = (i + 1 < deg) ? __ldg(&g_csrc[off + i + 1]) : 0;   // prefetch
        float v = lrelu(__ldg(&oas[s_cur * 8 + h]) + adh);
        float ex = __expf(v - mh) * inv;
        const float* sp = g_h1 + (size_t)s_cur * D1V + base;
        float4 a0 = __ldg((const float4*)sp);
        float4 a1 = __ldg((const float4*)(sp + 4));
        acc[0] += a0.x * ex; acc[1] += a0.y * ex; acc[2] += a0.z * ex; acc[3] += a0.w * ex;
        acc[4] += a1.x * ex; acc[5] += a1.y * ex; acc[6] += a1.z * ex; acc[7] += a1.w * ex;
        s_cur = s_nxt;
    }
    float4 bb0 = __ldg((const float4*)(b + base));
    float4 bb1 = __ldg((const float4*)(b + base + 4));
    float4 o0, o1;
    o0.x = fmaxf(acc[0] + bb0.x, 0.f); o0.y = fmaxf(acc[1] + bb0.y, 0.f);
    o0.z = fmaxf(acc[2] + bb0.z, 0.f); o0.w = fmaxf(acc[3] + bb0.w, 0.f);
    o1.x = fmaxf(acc[4] + bb1.x, 0.f); o1.y = fmaxf(acc[5] + bb1.y, 0.f);
    o1.z = fmaxf(acc[6] + bb1.z, 0.f); o1.w = fmaxf(acc[7] + bb1.w, 0.f);
    float* op = g_agg1 + (size_t)d * D1V + base;
    *(float4*)op       = o0;
    *(float4*)(op + 4) = o1;
}

// ---------------- layer 2: fused max+sum, warp per dst (HEADS=1) ----------------
__global__ void __launch_bounds__(256)
pass_ab2_kernel(const float* __restrict__ oas, const float* __restrict__ oad) {
    int d = (blockIdx.x * blockDim.x + threadIdx.x) >> 5;
    if (d >= NN) return;
    int lane = threadIdx.x & 31;
    int off = g_rowptr[d], deg = g_deg[d];
    float add = __ldg(&oad[d]);
    float m_run = NEGBIG, s_run = 0.f;
    for (int i = lane; i < deg; i += 32) {
        int s = __ldg(&g_csrc[off + i]);
        float v = lrelu(__ldg(&oas[s]) + add);
        float mnew = fmaxf(m_run, v);
        s_run = s_run * __expf(m_run - mnew) + __expf(v - mnew);
        m_run = mnew;
    }
#pragma unroll
    for (int o = 1; o <= 16; o <<= 1) {
        float mo = __shfl_xor_sync(0xFFFFFFFFu, m_run, o);
        float so = __shfl_xor_sync(0xFFFFFFFFu, s_run, o);
        float mnew = fmaxf(m_run, mo);
        s_run = s_run * __expf(m_run - mnew) + so * __expf(mo - mnew);
        m_run = mnew;
    }
    if (lane == 0) {
        g_m2[d] = m_run;
        g_s2[d] = s_run;
    }
}

// ---------------- layer 2: aggregation + bias + log_softmax, warp per dst ----------------
__global__ void __launch_bounds__(256)
pass_c2_kernel(const float* __restrict__ oas, const float* __restrict__ oad,
               const float* __restrict__ b, float* __restrict__ out) {
    int d = (blockIdx.x * blockDim.x + threadIdx.x) >> 5;
    if (d >= NN) return;
    int lane = threadIdx.x & 31;
    int c0 = lane * 2;
    int off = g_rowptr[d], deg = g_deg[d];
    float mh  = __ldg(&g_m2[d]);
    float inv = 1.f / (__ldg(&g_s2[d]) + EPS_SM);
    float add = __ldg(&oad[d]);
    float acc0 = 0.f, acc1 = 0.f;
    int s_cur = (deg > 0) ? __ldg(&g_csrc[off]) : 0;
    for (int i = 0; i < deg; i++) {
        int s_nxt = (i + 1 < deg) ? __ldg(&g_csrc[off + i + 1]) : 0;   // prefetch
        float v = lrelu(__ldg(&oas[s_cur]) + add);
        float ex = __expf(v - mh) * inv;
        float2 hv = __ldg((const float2*)(g_h2 + (size_t)s_cur * D2V + c0));
        acc0 += hv.x * ex;
        acc1 += hv.y * ex;
        s_cur = s_nxt;
    }
    float v0 = acc0 + __ldg(&b[c0]);
    float v1 = acc1 + __ldg(&b[c0 + 1]);
    float mx = fmaxf(v0, v1);
#pragma unroll
    for (int o = 16; o; o >>= 1) mx = fmaxf(mx, __shfl_xor_sync(0xFFFFFFFFu, mx, o));
    float se = __expf(v0 - mx) + __expf(v1 - mx);
#pragma unroll
    for (int o = 16; o; o >>= 1) se += __shfl_xor_sync(0xFFFFFFFFu, se, o);
    float l = mx + logf(se);
    out[(size_t)d * D2V + c0]     = v0 - l;
    out[(size_t)d * D2V + c0 + 1] = v1 - l;
}

// ---------------- host launch ----------------
extern "C" void kernel_launch(void* const* d_in, const int* in_sizes, int n_in,
                              void* d_out, int out_size) {
    const float* x        = (const float*)d_in[0];
    const void*  ei       = d_in[1];
    const float* W1       = (const float*)d_in[2];
    const float* att_src1 = (const float*)d_in[3];
    const float* att_dst1 = (const float*)d_in[4];
    const float* b1       = (const float*)d_in[5];
    const float* W2       = (const float*)d_in[6];
    const float* att_src2 = (const float*)d_in[7];
    const float* att_dst2 = (const float*)d_in[8];
    const float* b2       = (const float*)d_in[9];
    float* out = (float*)d_out;

    float *h1, *agg1, *h2, *as1, *ad1, *as2, *ad2;
    int *degp;
    cudaGetSymbolAddress((void**)&h1,   g_h1);
    cudaGetSymbolAddress((void**)&agg1, g_agg1);
    cudaGetSymbolAddress((void**)&h2,   g_h2);
    cudaGetSymbolAddress((void**)&as1,  g_as1);
    cudaGetSymbolAddress((void**)&ad1,  g_ad1);
    cudaGetSymbolAddress((void**)&as2,  g_as2);
    cudaGetSymbolAddress((void**)&ad2,  g_ad2);
    cudaGetSymbolAddress((void**)&degp, g_deg);

    // edge-index normalization (handles int32 or int64 delivery)
    detect_kernel<<<1, 1>>>(ei);
    convert_kernel<<<(2 * NE + 255) / 256, 256>>>(ei);

    // CSR build (re-done every launch; deterministic set, order-free math downstream)
    cudaMemsetAsync(degp, 0, sizeof(int) * NN);
    hist_kernel<<<(NEP + 255) / 256, 256>>>();
    scan1_kernel<<<NB, SCAN_CHUNK>>>();
    scan2_kernel<<<1, 128>>>();
    scan3_kernel<<<(NN + 255) / 256, 256>>>();
    scatter_kernel<<<(NEP + 255) / 256, 256>>>();

    const int WG = (NN * 32 + 255) / 256;   // warp-per-dst grids

    // ---- layer 1 ----
    tf32_gemm_kernel<<<dim3((NN + GBM - 1) / GBM, D1V / GBN), 256>>>(x, W1, h1, NN, D1V, FIN);
    dots_kernel<<<(NN * H1V + 255) / 256, 256>>>(h1, att_src1, att_dst1, as1, ad1, H1V, C1V);
    pass_ab1_kernel<<<WG, 256>>>(as1, ad1);
    pass_c1_kernel<<<WG, 256>>>(as1, ad1, b1);

    // ---- layer 2 ----
    sgemm_kernel<128, 64, 16, 8, 4>
        <<<dim3((NN + 127) / 128, 1), dim3(16, 16)>>>(agg1, W2, h2, NN, D2V, D1V);
    dots_kernel<<<(NN + 255) / 256, 256>>>(h2, att_src2, att_dst2, as2, ad2, 1, D2V);
    pass_ab2_kernel<<<WG, 256>>>(as2, ad2);
    pass_c2_kernel<<<WG, 256>>>(as2, ad2, b2, out);
}